// round 3
// baseline (speedup 1.0000x reference)
#include <cuda_runtime.h>

#define B_   2
#define M_   100
#define BM   200           // B_*M_
#define K_   6400
#define D_   1024
#define N_   128
#define P_   80            // patch grid side (80*80 = 6400)
#define DSPL 16            // d-split for kernel2 (1024/64)

// Scratch (static __device__ — no allocations allowed)
static __device__ float g_t[BM * D_];            // t[b,m,d]  (800 KB)
static __device__ float g_part[DSPL * BM * N_];  // partial GEMM sums (1.6 MB)

// PyTorch bicubic weight, a = -0.75, x >= 0
__device__ __forceinline__ float bicubic_w(float x) {
    if (x <= 1.0f) return (1.25f * x - 2.25f) * x * x + 1.0f;
    if (x < 2.0f)  return ((-0.75f * x + 3.75f) * x - 6.0f) * x + 3.0f;
    return 0.0f;
}

// u[h] = sum over output rows H in [lo, hi) of Mh[H, h]  (560 -> 80, ratio 7)
// src(H) = (H+0.5)/7 - 0.5 = (H-3)/7  =>  f = floor((H-3)/7) exactly in ints.
// Rows that can contribute to column h (incl. edge clipping) lie in [7h-11, 7h+17).
__device__ __forceinline__ float colsum(int h, int lo, int hi_excl) {
    int Hlo = max(lo, 7 * h - 11);
    int Hhi = min(hi_excl, 7 * h + 17);
    float acc = 0.0f;
    for (int H = Hlo; H < Hhi; ++H) {
        int f = (H >= 3) ? (H - 3) / 7 : -1;
        float t = (H + 0.5f) * (1.0f / 7.0f) - 0.5f - (float)f;
#pragma unroll
        for (int kk = -1; kk <= 2; ++kk) {
            int idx = f + kk;
            idx = min(max(idx, 0), P_ - 1);
            if (idx == h) acc += bicubic_w(fabsf(t - (float)kk));
        }
    }
    return acc;
}

// ---------------------------------------------------------------------------
// Kernel 1: per-(box, d-chunk) gather:  t[bm, d] = sum_{h,w} u[h] v[w] feats
// grid (BM, 4), 256 threads; thread owns one d of a 256-wide chunk.
// ---------------------------------------------------------------------------
__global__ __launch_bounds__(256) void k1_gather(const float* __restrict__ feats,
                                                 const int*   __restrict__ boxes) {
    const int bm = blockIdx.x;
    const int b  = bm / M_;
    const int4 bx = ((const int4*)boxes)[bm];   // x1, y1, w, h
    const int x1 = bx.x, y1 = bx.y;
    const int xe = x1 + bx.z - 1;               // exclusive end (cols)
    const int ye = y1 + bx.w - 1;               // exclusive end (rows)

    __shared__ float su[P_], sv[P_];
    const int tid = threadIdx.x;
    if (tid < P_)                      su[tid]       = colsum(tid,       y1, ye);
    else if (tid >= 128 && tid < 128 + P_) sv[tid - 128] = colsum(tid - 128, x1, xe);
    __syncthreads();

    // support range (slightly over-inclusive is fine; zero rows skipped below)
    int hlo = y1 - 10; hlo = (hlo > 0) ? hlo / 7 : 0;
    int hhi = min(P_ - 1, (ye + 10) / 7);
    int wlo = x1 - 10; wlo = (wlo > 0) ? wlo / 7 : 0;
    int whi = min(P_ - 1, (xe + 10) / 7);
    const int nw = whi - wlo + 1;

    const int d = blockIdx.y * 256 + tid;
    const float* fb = feats + (size_t)b * (K_ * D_) + d;

    float acc = 0.0f;
    for (int ih = hlo; ih <= hhi; ++ih) {
        const float cu = su[ih];
        if (cu == 0.0f) continue;
        const float* p = fb + (size_t)(ih * P_ + wlo) * D_;
#pragma unroll 4
        for (int iw = 0; iw < nw; ++iw) {
            acc = fmaf(cu * sv[wlo + iw], __ldg(p + (size_t)iw * D_), acc);
        }
    }
    g_t[bm * D_ + d] = acc;
}

// ---------------------------------------------------------------------------
// Kernel 2: partial GEMM  part[s, bm, n] = sum_{d in slice s} t[bm,d] emb[n,d]
// grid (25, 16): block = 8 bm x 128 n x 64 d. Shared-tiled, float4 inner.
// ---------------------------------------------------------------------------
__global__ __launch_bounds__(256) void k2_gemm(const float* __restrict__ emb) {
    __shared__ float s_e[N_ * 68];   // 68-float row pitch: conflict-free + 16B aligned
    __shared__ float s_t[8 * 64];

    const int tid = threadIdx.x;
    const int bm0 = blockIdx.x * 8;
    const int ds  = blockIdx.y * 64;

    for (int i = tid; i < N_ * 64; i += 256) {
        int n = i >> 6, dd = i & 63;
        s_e[n * 68 + dd] = emb[n * D_ + ds + dd];
    }
    for (int i = tid; i < 8 * 64; i += 256) {
        int r = i >> 6, c = i & 63;
        s_t[i] = g_t[(bm0 + r) * D_ + ds + c];
    }
    __syncthreads();

    const int n    = tid & 127;
    const int half = tid >> 7;          // 0/1: which group of 4 bm rows
    const float4* e4 = (const float4*)(s_e + n * 68);
    const float4* t0 = (const float4*)(s_t + (half * 4 + 0) * 64);
    const float4* t1 = (const float4*)(s_t + (half * 4 + 1) * 64);
    const float4* t2 = (const float4*)(s_t + (half * 4 + 2) * 64);
    const float4* t3 = (const float4*)(s_t + (half * 4 + 3) * 64);

    float a0 = 0.f, a1 = 0.f, a2 = 0.f, a3 = 0.f;
#pragma unroll
    for (int q = 0; q < 16; ++q) {
        const float4 e = e4[q];
        float4 v;
        v = t0[q]; a0 += e.x * v.x + e.y * v.y + e.z * v.z + e.w * v.w;
        v = t1[q]; a1 += e.x * v.x + e.y * v.y + e.z * v.z + e.w * v.w;
        v = t2[q]; a2 += e.x * v.x + e.y * v.y + e.z * v.z + e.w * v.w;
        v = t3[q]; a3 += e.x * v.x + e.y * v.y + e.z * v.z + e.w * v.w;
    }

    float* outp = g_part + ((size_t)blockIdx.y * BM + bm0 + half * 4) * N_ + n;
    outp[0 * N_] = a0;
    outp[1 * N_] = a1;
    outp[2 * N_] = a2;
    outp[3 * N_] = a3;
}

// ---------------------------------------------------------------------------
// Kernel 3: deterministic reduction of 16 partials + divide by box area.
// ---------------------------------------------------------------------------
__global__ __launch_bounds__(256) void k3_reduce(const int* __restrict__ boxes,
                                                 float* __restrict__ out) {
    const int i = blockIdx.x * blockDim.x + threadIdx.x;
    if (i >= BM * N_) return;
    const int bm = i >> 7;
    float s = 0.0f;
#pragma unroll
    for (int p = 0; p < DSPL; ++p) s += g_part[p * (BM * N_) + i];
    const int4 bx = ((const int4*)boxes)[bm];
    const float area = (float)((bx.w - 1) * (bx.z - 1));
    out[i] = s / area;
}

extern "C" void kernel_launch(void* const* d_in, const int* in_sizes, int n_in,
                              void* d_out, int out_size) {
    const float* feats = nullptr;
    const float* emb   = nullptr;
    const int*   boxes = nullptr;
    for (int i = 0; i < n_in; ++i) {
        if      (in_sizes[i] == B_ * K_ * D_) feats = (const float*)d_in[i];
        else if (in_sizes[i] == N_ * D_)      emb   = (const float*)d_in[i];
        else if (in_sizes[i] == B_ * M_ * 4)  boxes = (const int*)d_in[i];
    }
    if (!feats) feats = (const float*)d_in[0];
    if (!emb)   emb   = (const float*)d_in[1];
    if (!boxes) boxes = (const int*)d_in[2];

    k1_gather<<<dim3(BM, 4), 256>>>(feats, boxes);
    k2_gemm<<<dim3(BM / 8, DSPL), 256>>>(emb);
    k3_reduce<<<(BM * N_ + 255) / 256, 256>>>(boxes, (float*)d_out);
}